// round 14
// baseline (speedup 1.0000x reference)
#include <cuda_runtime.h>
#include <cuda_fp16.h>
#include <math.h>
#include <stdint.h>

#define Tn 512
#define Bn 8
#define En 1024
#define Hn 1024
#define Dn 512
#define Vn 32000
#define MROWS (Tn * Bn)          // 4096, TIME-MAJOR: row m = t*Bn + b
#define KCAT 2048
#define NMI (MROWS / 128)        // 32 M-tiles (16 time-steps each)
#define NTILES (NMI * (Vn / 128))   // 8000 logits tiles
#define NUTILES (NMI * (Hn / 128))  // 256 U tiles
#define LAG 16
#define GTOT (Tn + LAG)          // 528 scan steps

__device__ float g_R0pre[MROWS * Dn];
__device__ float g_R1pre[MROWS * Dn];
__device__ float g_R0[MROWS * Dn];
__device__ float g_R1[MROWS * Dn];
__device__ float g_Hpre[MROWS * Hn];
__device__ float g_H[MROWS * Hn];
__device__ unsigned g_cnt;
__device__ unsigned g_prog;
__device__ unsigned g_uctr;
__device__ unsigned g_udone[NMI];
__device__ unsigned g_tilectr;

__device__ __half g_Xcat[(size_t)MROWS * KCAT];   // [X | R0 | R1] fp16, time-major
__device__ __half g_Wcat[(size_t)Hn * KCAT];      // [W_x | U0 | U1] fp16
__device__ __half g_Win0h[(size_t)Dn * En];
__device__ __half g_Win1h[(size_t)Dn * En];
__device__ __half g_Wh[(size_t)Vn * Hn];
__device__ __half g_Hh[(size_t)MROWS * Hn];

__device__ __forceinline__ uint32_t smem_u32(const void* p) {
    uint32_t a;
    asm("{ .reg .u64 t; cvta.to.shared.u64 t, %1; cvt.u32.u64 %0, t; }" : "=r"(a) : "l"(p));
    return a;
}
__device__ __forceinline__ void cp_async16(uint32_t saddr, const void* gaddr) {
    asm volatile("cp.async.cg.shared.global [%0], [%1], 16;" :: "r"(saddr), "l"(gaddr));
}
#define CP_COMMIT() asm volatile("cp.async.commit_group;" ::: "memory")
#define CP_WAIT(N)  asm volatile("cp.async.wait_group %0;" :: "n"(N) : "memory")
#define BARS(id)    asm volatile("bar.sync %0, 256;" :: "r"(id) : "memory")

__device__ __forceinline__ void ldsm_x4(uint32_t& r0, uint32_t& r1, uint32_t& r2,
                                        uint32_t& r3, uint32_t addr) {
    asm volatile("ldmatrix.sync.aligned.m8n8.x4.shared.b16 {%0,%1,%2,%3}, [%4];"
                 : "=r"(r0), "=r"(r1), "=r"(r2), "=r"(r3) : "r"(addr));
}
__device__ __forceinline__ void mma16816h(float* c, const uint32_t* a, const uint32_t* b) {
    asm volatile(
        "mma.sync.aligned.m16n8k16.row.col.f32.f16.f16.f32 "
        "{%0,%1,%2,%3}, {%4,%5,%6,%7}, {%8,%9}, {%0,%1,%2,%3};"
        : "+f"(c[0]), "+f"(c[1]), "+f"(c[2]), "+f"(c[3])
        : "r"(a[0]), "r"(a[1]), "r"(a[2]), "r"(a[3]), "r"(b[0]), "r"(b[1]));
}

// -------- launch 1: embedding gather (time-major) + counter reset -------------
__global__ void embed_h(const int* __restrict__ ids, const float* __restrict__ emb,
                        __half* __restrict__ Xcat)
{
    int blk = blockIdx.x;
    if (blk == 0 && threadIdx.x == 0) {
        g_cnt = 0u; g_prog = 0u; g_uctr = 0u; g_tilectr = 0u;
        for (int i = 0; i < NMI; ++i) g_udone[i] = 0u;
    }
    int b = blk / Tn, t = blk % Tn;
    int m = t * Bn + b;
    int id = __ldg(ids + blk);
    float4 v = __ldg(((const float4*)(emb + (size_t)id * En)) + threadIdx.x);
    __half2* dst = (__half2*)(Xcat + (size_t)m * KCAT) + threadIdx.x * 2;
    dst[0] = __floats2half2_rn(v.x, v.y);
    dst[1] = __floats2half2_rn(v.z, v.w);
}

// -------- launch 2: Win0 + Win1 -> fp16 ---------------------------------------
__global__ void cvt_win(const float* __restrict__ Win0, const float* __restrict__ Win1,
                        __half* __restrict__ W0h, __half* __restrict__ W1h)
{
    int i = blockIdx.x * blockDim.x + threadIdx.x;
    const int n4 = Dn * En / 4;
    const float* src; __half* dst; int k;
    if (i < n4) { src = Win0; dst = W0h; k = i; }
    else        { src = Win1; dst = W1h; k = i - n4; }
    float4 v = ((const float4*)src)[k];
    __half2* dp = (__half2*)dst;
    dp[k * 2 + 0] = __floats2half2_rn(v.x, v.y);
    dp[k * 2 + 1] = __floats2half2_rn(v.z, v.w);
}

// -------- launch 3: outW -> fp16  AND  pack [W_x|U0|U1] -> Wcat ---------------
#define NB_OUTW (Vn * Hn / 4 / 256)
__global__ void cvt_whpack(const float* __restrict__ outW, __half* __restrict__ Wh16,
                           const float* __restrict__ Wx, const float* __restrict__ U0,
                           const float* __restrict__ U1, __half* __restrict__ Wcat)
{
    if (blockIdx.x < NB_OUTW) {
        int i = blockIdx.x * 256 + threadIdx.x;
        float4 v = ((const float4*)outW)[i];
        __half2* dp = (__half2*)Wh16;
        dp[i * 2 + 0] = __floats2half2_rn(v.x, v.y);
        dp[i * 2 + 1] = __floats2half2_rn(v.z, v.w);
    } else {
        int n = blockIdx.x - NB_OUTW;
#pragma unroll
        for (int h = 0; h < 2; ++h) {
            int c = (threadIdx.x + h * 256) * 4;
            const float* src;
            if (c < En)            src = Wx + (size_t)n * En + c;
            else if (c < En + Dn)  src = U0 + (size_t)n * Dn + (c - En);
            else                   src = U1 + (size_t)n * Dn + (c - En - Dn);
            float4 v = *(const float4*)src;
            __half2* p = (__half2*)(Wcat + (size_t)n * KCAT + c);
            p[0] = __floats2half2_rn(v.x, v.y);
            p[1] = __floats2half2_rn(v.z, v.w);
        }
    }
}

#define KCH 64
#define TILEB (128 * KCH * 2)
#define STAGEB (2 * TILEB)
#define MEGA_SMEM (160 * 1024)

// ---- tile-GEMM body for a 256-thread pool synced by named barrier `barid`.
// flags: 1=bias, 2=accumulate, 4=time->batch row remap.
__device__ __forceinline__ void gemm_tile(
    uint32_t sbase, int htid, int lane, int wm, int wn, int barid,
    const __half* gA, const __half* gB, int lda, int ldb, int K,
    const float* bias, float* C, int ldc, int m0, int n0, int flags)
{
    float acc[4][4][4];
#pragma unroll
    for (int a = 0; a < 4; a++)
#pragma unroll
        for (int bq = 0; bq < 4; bq++)
#pragma unroll
            for (int cx = 0; cx < 4; cx++) acc[a][bq][cx] = 0.f;

    auto issue_stage = [&](int s, int kc) {
        uint32_t stb = sbase + s * STAGEB;
        const __half* ga = gA + kc * KCH;
#pragma unroll
        for (int i = 0; i < 4; ++i) {
            int q = htid + i * 256;
            int r = q >> 3, c = q & 7;
            uint32_t sa = stb + ((r >> 3) << 10) + ((r & 7) << 7) + ((c ^ (r & 7)) << 4);
            cp_async16(sa, ga + (size_t)r * lda + c * 8);
        }
        const __half* gb = gB + kc * KCH;
        uint32_t tb = stb + TILEB;
#pragma unroll
        for (int i = 0; i < 4; ++i) {
            int q = htid + i * 256;
            int r = q >> 3, c = q & 7;
            uint32_t sa = tb + ((r >> 3) << 10) + ((r & 7) << 7) + ((c ^ (r & 7)) << 4);
            cp_async16(sa, gb + (size_t)r * ldb + c * 8);
        }
    };

    issue_stage(0, 0);
    CP_COMMIT();

    const int NKC = K / KCH;
    for (int kc = 0; kc < NKC; ++kc) {
        if (kc + 1 < NKC) { issue_stage((kc + 1) & 1, kc + 1); CP_COMMIT(); CP_WAIT(1); }
        else { CP_WAIT(0); }
        BARS(barid);

        uint32_t sA = sbase + (kc & 1) * STAGEB;
        uint32_t sB = sA + TILEB;

#pragma unroll
        for (int ks = 0; ks < KCH / 16; ++ks) {
            uint32_t ah[4][4], bh[4][2];
            int ra = (lane & 7) + ((lane >> 3) & 1) * 8;
            int ca = ks * 2 + ((lane >> 4) & 1);
#pragma unroll
            for (int mt = 0; mt < 4; ++mt) {
                int row = wm * 64 + mt * 16 + ra;
                uint32_t off = ((row >> 3) << 10) + ((row & 7) << 7)
                             + (((ca ^ (row & 7)) & 7) << 4);
                ldsm_x4(ah[mt][0], ah[mt][1], ah[mt][2], ah[mt][3], sA + off);
            }
            int rb = (lane & 7) + ((lane >> 4) & 1) * 8;
            int cb = ks * 2 + ((lane >> 3) & 1);
#pragma unroll
            for (int np = 0; np < 2; ++np) {
                int row = wn * 32 + np * 16 + rb;
                uint32_t off = ((row >> 3) << 10) + ((row & 7) << 7)
                             + (((cb ^ (row & 7)) & 7) << 4);
                ldsm_x4(bh[np * 2][0], bh[np * 2][1],
                        bh[np * 2 + 1][0], bh[np * 2 + 1][1], sB + off);
            }
#pragma unroll
            for (int mt = 0; mt < 4; ++mt)
#pragma unroll
                for (int nt = 0; nt < 4; ++nt)
                    mma16816h(acc[mt][nt], ah[mt], bh[nt]);
        }
        BARS(barid);
    }

#pragma unroll
    for (int mt = 0; mt < 4; ++mt) {
        int r0g = m0 + wm * 64 + mt * 16 + (lane >> 2);
        int r1g = r0g + 8;
        int row0 = (flags & 4) ? (((r0g & 7) << 9) | (r0g >> 3)) : r0g;
        int row1 = (flags & 4) ? (((r1g & 7) << 9) | (r1g >> 3)) : r1g;
#pragma unroll
        for (int nt = 0; nt < 4; ++nt) {
            int cc = n0 + wn * 32 + nt * 8 + (lane & 3) * 2;
            float bx = 0.f, by = 0.f;
            if (flags & 1) { float2 bia = *(const float2*)(bias + cc); bx = bia.x; by = bia.y; }
            float* p0 = C + (size_t)row0 * ldc + cc;
            float* p1 = C + (size_t)row1 * ldc + cc;
            float2 v0 = make_float2(acc[mt][nt][0] + bx, acc[mt][nt][1] + by);
            float2 v1 = make_float2(acc[mt][nt][2] + bx, acc[mt][nt][3] + by);
            if (flags & 2) {
                float2 o0 = *(float2*)p0, o1 = *(float2*)p1;
                v0.x += o0.x; v0.y += o0.y; v1.x += o1.x; v1.y += o1.y;
            }
            *(float2*)p0 = v0;
            *(float2*)p1 = v1;
        }
    }
}

// -------- launches 4,5: standalone GEMMs (bar 0 == full 256-thread block) -----
__global__ void __launch_bounds__(256, 2)
gemm16(const __half* __restrict__ A, const __half* __restrict__ W,
       const float* __restrict__ bias, float* __restrict__ C,
       const __half* __restrict__ W1, float* __restrict__ C1,
       int N, int K, int lda, int ldb, int flags)
{
    extern __shared__ __align__(16) char sm[];
    uint32_t sbase = smem_u32(sm);
    if (blockIdx.z) { W = W1; C = C1; }
    int tid = threadIdx.x, lane = tid & 31, wid = tid >> 5;
    gemm_tile(sbase, tid, lane, wid >> 2, wid & 3, 0,
              A + (size_t)blockIdx.x * 128 * lda, W + (size_t)blockIdx.y * 128 * ldb,
              lda, ldb, K, bias, C, N, blockIdx.x * 128, blockIdx.y * 128, flags);
}

// -------- gemm worker loops (used by gemm halves and draining scan halves) ----
__device__ void worker_loops(uint32_t gbase, int htid, int lane, int wm, int wn,
                             int barid, unsigned* s_q,
                             __half* Xcat, const __half* Wcat, float* Hpre,
                             const __half* Hh, const __half* Wlg,
                             const float* bias, float* C, bool do_u)
{
    if (do_u) {
        for (;;) {
            if (htid == 0) *s_q = atomicAdd(&g_uctr, 1u);
            BARS(barid);
            unsigned q = *s_q;
            BARS(barid);
            if (q >= NUTILES) break;
            int mi = q >> 3, ni = q & 7;
            if (htid == 0) {
                unsigned need = (unsigned)(mi + 1) * 16u;
                while (*(volatile unsigned*)&g_prog < need) __nanosleep(128);
            }
            BARS(barid);
            __threadfence();
            gemm_tile(gbase, htid, lane, wm, wn, barid,
                      Xcat + En + (size_t)mi * 128 * KCAT,
                      Wcat + En + (size_t)ni * 128 * KCAT,
                      KCAT, KCAT, 1024, nullptr, Hpre, Hn,
                      mi * 128, ni * 128, 2);
            __threadfence();
            if (htid == 0) atomicAdd(&g_udone[mi], 1u);
            BARS(barid);
        }
    }
    for (;;) {
        if (htid == 0) *s_q = atomicAdd(&g_tilectr, 1u);
        BARS(barid);
        unsigned tile = *s_q;
        BARS(barid);
        if (tile >= NTILES) break;
        int mi = tile / 250, ni = tile % 250;
        if (htid == 0) {
            unsigned need = (unsigned)(mi + 2) * 16u;
            while (*(volatile unsigned*)&g_prog < need) __nanosleep(128);
        }
        BARS(barid);
        __threadfence();
        gemm_tile(gbase, htid, lane, wm, wn, barid,
                  Hh + (size_t)mi * 128 * Hn, Wlg + (size_t)ni * 128 * Hn,
                  Hn, Hn, Hn, bias, C, Vn, mi * 128, ni * 128, 1 | 4);
    }
}

// -------- launch 5(mega): 148 CTAs x 512 threads, warp-specialized ------------
// CTA<128 halfA: fused scan (r at step g, h at t=g-16), barrier pop=128, bar 1.
// All other halves: GEMM workers (bar 2 / bar 3). Scan halves drain after.
__global__ void __launch_bounds__(512, 1)
crsd_mega(const float* __restrict__ pre0, const float* __restrict__ pre1,
          const float* __restrict__ Wr0, const float* __restrict__ Wr1,
          float* __restrict__ R0, float* __restrict__ R1,
          __half* __restrict__ Xcat, const __half* __restrict__ Wcat,
          float* __restrict__ Hpre, const float* __restrict__ Whw,
          float* __restrict__ Hout, __half* __restrict__ Hh,
          const __half* __restrict__ Wlg, const float* __restrict__ bias,
          float* __restrict__ C)
{
    extern __shared__ __align__(16) char sm[];
    __shared__ unsigned s_q[4];
    int cta = blockIdx.x;
    int tid = threadIdx.x;
    int half = tid >> 8, htid = tid & 255;
    int lane = htid & 31, hw = htid >> 5;
    int wm = hw >> 2, wn = hw & 3;

    bool scan_role = (cta < 128 && half == 0);
    int barid = scan_role ? 1 : (half == 0 ? 2 : (cta < 128 ? 2 : 3));
    uint32_t gbase = smem_u32(sm) + (scan_role ? 0u
                     : (half == 0 ? 0u : (uint32_t)(96 * 1024)));
    // CTA<128 halfB uses 96K region; CTA>=128: halfA 0, halfB 96K.
    if (cta < 128 && half == 1) gbase = smem_u32(sm) + 96 * 1024;

    if (scan_role) {
        float* smf = (float*)sm;
        float* sWr = smf;                    // 8*512   (16KB)
        float* sWh = smf + 8 * Dn;           // 8*1024  (32KB)
        float* sR  = smf + 8 * Dn + 8 * Hn;  // Bn*512  (16KB)
        float* sH  = sR + Bn * Dn;           // Bn*1024 (32KB)
        int res = cta >> 6;
        int j0r = (cta & 63) * 8;
        int j0h = cta * 8;
        const float* pre  = res ? pre1 : pre0;
        const float* Wres = res ? Wr1 : Wr0;
        float* Rout = res ? R1 : R0;
        int b = htid >> 5;

        for (int i = htid; i < 8 * Dn / 4; i += 256)
            ((float4*)sWr)[i] = ((const float4*)(Wres + (size_t)j0r * Dn))[i];
        for (int i = htid; i < 8 * Hn / 4; i += 256)
            ((float4*)sWh)[i] = ((const float4*)(Whw + (size_t)j0h * Hn))[i];
        BARS(1);

        for (int g = 0; g < GTOT; ++g) {
            // ---- state loads
            if (g < Tn) {
                if (g == 0) {
                    float4 z = make_float4(0.f, 0.f, 0.f, 0.f);
                    for (int i = htid; i < Bn * Dn / 4; i += 256) ((float4*)sR)[i] = z;
                } else {
                    const float4* src = (const float4*)(Rout + (size_t)(g - 1) * Bn * Dn);
                    for (int i = htid; i < Bn * Dn / 4; i += 256)
                        ((float4*)sR)[i] = __ldcg(src + i);
                }
            }
            if (g >= LAG) {
                int t = g - LAG;
                if (t == 0) {
                    float4 z = make_float4(0.f, 0.f, 0.f, 0.f);
                    for (int i = htid; i < Bn * Hn / 4; i += 256) ((float4*)sH)[i] = z;
                } else {
                    const float4* src = (const float4*)(Hout + (size_t)(t - 1) * Bn * Hn);
                    for (int i = htid; i < Bn * Hn / 4; i += 256)
                        ((float4*)sH)[i] = __ldcg(src + i);
                }
            }
            BARS(1);

            // ---- r step (g < Tn)
            if (g < Tn) {
                const float4* rb = (const float4*)(sR + b * Dn);
                float4 rv[4];
#pragma unroll
                for (int i = 0; i < 4; i++) rv[i] = rb[i * 32 + lane];
                float s[8];
#pragma unroll
                for (int jj = 0; jj < 8; ++jj) {
                    const float4* wr = (const float4*)(sWr + jj * Dn);
                    float sv = 0.f;
#pragma unroll
                    for (int i = 0; i < 4; i++) {
                        float4 w4 = wr[i * 32 + lane];
                        sv += rv[i].x * w4.x + rv[i].y * w4.y + rv[i].z * w4.z + rv[i].w * w4.w;
                    }
                    s[jj] = sv;
                }
#pragma unroll
                for (int off = 16; off; off >>= 1)
#pragma unroll
                    for (int jj = 0; jj < 8; ++jj)
                        s[jj] += __shfl_xor_sync(0xffffffffu, s[jj], off);
                float myout = 0.f;
#pragma unroll
                for (int jj = 0; jj < 8; ++jj)
                    if (lane == jj) myout = s[jj];
                if (lane < 8) {
                    int j = j0r + lane;
                    size_t row = (size_t)g * Bn + b;
                    float rold = sR[b * Dn + j];
                    float p = __ldcg(pre + row * Dn + j);
                    float val = 0.5f * rold + 0.5f * tanhf(p + myout);
                    Rout[row * Dn + j] = val;
                    Xcat[row * KCAT + En + res * Dn + j] = __float2half(val);
                }
            }

            // ---- h step (t = g - LAG)
            if (g >= LAG) {
                int t = g - LAG;
                if ((t & 15) == 0) {
                    if (htid == 0) {
                        int mi = t >> 4;
                        while (*(volatile unsigned*)&g_udone[mi] < 8u) __nanosleep(128);
                        __threadfence();
                    }
                    BARS(1);
                }
                const float4* hb = (const float4*)(sH + b * Hn);
                float4 hv[8];
#pragma unroll
                for (int i = 0; i < 8; i++) hv[i] = hb[i * 32 + lane];
                float s[8];
#pragma unroll
                for (int jj = 0; jj < 8; ++jj) {
                    const float4* wr = (const float4*)(sWh + jj * Hn);
                    float sv = 0.f;
#pragma unroll
                    for (int i = 0; i < 8; i++) {
                        float4 w4 = wr[i * 32 + lane];
                        sv += hv[i].x * w4.x + hv[i].y * w4.y + hv[i].z * w4.z + hv[i].w * w4.w;
                    }
                    s[jj] = sv;
                }
#pragma unroll
                for (int off = 16; off; off >>= 1)
#pragma unroll
                    for (int jj = 0; jj < 8; ++jj)
                        s[jj] += __shfl_xor_sync(0xffffffffu, s[jj], off);
                float myout = 0.f;
#pragma unroll
                for (int jj = 0; jj < 8; ++jj)
                    if (lane == jj) myout = s[jj];
                if (lane < 8) {
                    int j = j0h + lane;
                    size_t row = (size_t)t * Bn + b;
                    float val = tanhf(__ldcg(Hpre + row * Hn + j) + myout);
                    Hout[row * Hn + j] = val;
                    Hh[row * Hn + j] = __float2half(val);
                }
            }
            BARS(1);

            // ---- grid barrier over the 128 scan halves
            if (htid == 0) {
                __threadfence();
                atomicAdd(&g_cnt, 1u);
                while (*(volatile unsigned*)&g_cnt < 128u * (unsigned)(g + 1))
                    __nanosleep(32);
                __threadfence();
            }
            BARS(1);
            if (cta == 0 && htid == 0)
                *(volatile unsigned*)&g_prog = (unsigned)(g + 1);
        }
        // drain into logits (reuse scan smem region as gemm buffers)
        worker_loops(smem_u32(sm), htid, lane, wm, wn, 1, &s_q[0],
                     Xcat, Wcat, Hpre, Hh, Wlg, bias, C, false);
    } else {
        worker_loops(gbase, htid, lane, wm, wn, barid, &s_q[barid],
                     Xcat, Wcat, Hpre, Hh, Wlg, bias, C, true);
    }
}

extern "C" void kernel_launch(void* const* d_in, const int* in_sizes, int n_in,
                              void* d_out, int out_size)
{
    const int*   ids   = (const int*)  d_in[0];
    const float* emb   = (const float*)d_in[1];
    const float* W_x   = (const float*)d_in[2];
    const float* W_h   = (const float*)d_in[3];
    const float* b_h   = (const float*)d_in[4];
    const float* Win0  = (const float*)d_in[5];
    const float* Wres0 = (const float*)d_in[6];
    const float* U0    = (const float*)d_in[7];
    const float* Win1  = (const float*)d_in[8];
    const float* Wres1 = (const float*)d_in[9];
    const float* U1    = (const float*)d_in[10];
    const float* outW  = (const float*)d_in[11];
    const float* outb  = (const float*)d_in[12];
    float* out = (float*)d_out;

    float *R0pre, *R1pre, *R0, *R1, *Hpre, *Hst;
    __half *Xcat, *Wcat, *Win0h, *Win1h, *Wh16, *Hh16;
    cudaGetSymbolAddress((void**)&R0pre, g_R0pre);
    cudaGetSymbolAddress((void**)&R1pre, g_R1pre);
    cudaGetSymbolAddress((void**)&R0,    g_R0);
    cudaGetSymbolAddress((void**)&R1,    g_R1);
    cudaGetSymbolAddress((void**)&Hpre,  g_Hpre);
    cudaGetSymbolAddress((void**)&Hst,   g_H);
    cudaGetSymbolAddress((void**)&Xcat,  g_Xcat);
    cudaGetSymbolAddress((void**)&Wcat,  g_Wcat);
    cudaGetSymbolAddress((void**)&Win0h, g_Win0h);
    cudaGetSymbolAddress((void**)&Win1h, g_Win1h);
    cudaGetSymbolAddress((void**)&Wh16,  g_Wh);
    cudaGetSymbolAddress((void**)&Hh16,  g_Hh);

    cudaFuncSetAttribute(gemm16,
                         cudaFuncAttributeMaxDynamicSharedMemorySize, 2 * STAGEB);
    cudaFuncSetAttribute(crsd_mega,
                         cudaFuncAttributeMaxDynamicSharedMemorySize, MEGA_SMEM);

    // (1) embedding gather + counter reset
    embed_h<<<MROWS, 256>>>(ids, emb, Xcat);

    // (2) Win0/Win1 -> fp16
    cvt_win<<<2 * (Dn * En / 4) / 256, 256>>>(Win0, Win1, Win0h, Win1h);

    // (3) outW -> fp16  +  pack [W_x|U0|U1] -> Wcat
    cvt_whpack<<<NB_OUTW + Hn, 256>>>(outW, Wh16, W_x, U0, U1, Wcat);

    // (4) reservoir input projections (dual via z)
    gemm16<<<dim3(MROWS / 128, Dn / 128, 2), 256, 2 * STAGEB>>>(
        Xcat, Win0h, nullptr, R0pre, Win1h, R1pre, Dn, En, KCAT, En, 0);

    // (5) Hpre_x = X @ W_x^T + b_h
    gemm16<<<dim3(MROWS / 128, Hn / 128, 1), 256, 2 * STAGEB>>>(
        Xcat, Wcat, b_h, Hpre, nullptr, nullptr, Hn, En, KCAT, KCAT, 1);

    // (6) mega-kernel: warp-specialized scan+GEMM on every SM
    crsd_mega<<<148, 512, MEGA_SMEM>>>(
        R0pre, R1pre, Wres0, Wres1, R0, R1, Xcat, Wcat,
        Hpre, W_h, Hst, Hh16, Wh16, outb, out);
}

// round 15
// speedup vs baseline: 1.1729x; 1.1729x over previous
#include <cuda_runtime.h>
#include <cuda_fp16.h>
#include <math.h>
#include <stdint.h>

#define Tn 512
#define Bn 8
#define En 1024
#define Hn 1024
#define Dn 512
#define Vn 32000
#define MROWS (Tn * Bn)          // 4096, TIME-MAJOR: row m = t*Bn + b
#define KCAT 2048
#define NMI (MROWS / 128)        // 32 M-tiles, each spans 16 time-steps
#define NTILES (NMI * (Vn / 128))   // 8000 logits tiles
#define NUTILES (NMI * (Hn / 128))  // 256 U tiles

__device__ float g_R0pre[MROWS * Dn];
__device__ float g_R1pre[MROWS * Dn];
__device__ float g_R0[MROWS * Dn];
__device__ float g_R1[MROWS * Dn];
__device__ float g_Hpre[MROWS * Hn];
__device__ float g_H[MROWS * Hn];
// flag/publish barrier state (reset by embed_h each launch)
__device__ unsigned g_flagR[128 * 32];   // rscan per-CTA flags, 128B stride
__device__ unsigned g_flagH[128 * 32];   // hscan per-CTA flags
__device__ unsigned g_tokR[32];          // rscan progress token (== g_prog_r)
__device__ unsigned g_tokH[32];          // hscan progress token (== g_prog)
__device__ unsigned g_uctr;
__device__ unsigned g_udone[NMI];
__device__ unsigned g_tilectr;

__device__ __half g_Xcat[(size_t)MROWS * KCAT];   // [X | R0 | R1] fp16, time-major
__device__ __half g_Wcat[(size_t)Hn * KCAT];      // [W_x | U0 | U1] fp16
__device__ __half g_Win0h[(size_t)Dn * En];
__device__ __half g_Win1h[(size_t)Dn * En];
__device__ __half g_Wh[(size_t)Vn * Hn];
__device__ __half g_Hh[(size_t)MROWS * Hn];

__device__ __forceinline__ uint32_t smem_u32(const void* p) {
    uint32_t a;
    asm("{ .reg .u64 t; cvta.to.shared.u64 t, %1; cvt.u32.u64 %0, t; }" : "=r"(a) : "l"(p));
    return a;
}
__device__ __forceinline__ void cp_async16(uint32_t saddr, const void* gaddr) {
    asm volatile("cp.async.cg.shared.global [%0], [%1], 16;" :: "r"(saddr), "l"(gaddr));
}
#define CP_COMMIT() asm volatile("cp.async.commit_group;" ::: "memory")
#define CP_WAIT(N)  asm volatile("cp.async.wait_group %0;" :: "n"(N) : "memory")

__device__ __forceinline__ void ldsm_x4(uint32_t& r0, uint32_t& r1, uint32_t& r2,
                                        uint32_t& r3, uint32_t addr) {
    asm volatile("ldmatrix.sync.aligned.m8n8.x4.shared.b16 {%0,%1,%2,%3}, [%4];"
                 : "=r"(r0), "=r"(r1), "=r"(r2), "=r"(r3) : "r"(addr));
}
__device__ __forceinline__ void mma16816h(float* c, const uint32_t* a, const uint32_t* b) {
    asm volatile(
        "mma.sync.aligned.m16n8k16.row.col.f32.f16.f16.f32 "
        "{%0,%1,%2,%3}, {%4,%5,%6,%7}, {%8,%9}, {%0,%1,%2,%3};"
        : "+f"(c[0]), "+f"(c[1]), "+f"(c[2]), "+f"(c[3])
        : "r"(a[0]), "r"(a[1]), "r"(a[2]), "r"(a[3]), "r"(b[0]), "r"(b[1]));
}

// -------- launch 1: embedding gather (time-major) + state reset ---------------
__global__ void embed_h(const int* __restrict__ ids, const float* __restrict__ emb,
                        __half* __restrict__ Xcat)
{
    int blk = blockIdx.x;
    if (blk == 0 && threadIdx.x == 0) {
        g_uctr = 0u; g_tilectr = 0u;
        g_tokR[0] = 0u; g_tokH[0] = 0u;
        for (int i = 0; i < NMI; ++i) g_udone[i] = 0u;
        for (int i = 0; i < 128; ++i) { g_flagR[i * 32] = 0u; g_flagH[i * 32] = 0u; }
    }
    int b = blk / Tn, t = blk % Tn;
    int m = t * Bn + b;
    int id = __ldg(ids + blk);
    float4 v = __ldg(((const float4*)(emb + (size_t)id * En)) + threadIdx.x);
    __half2* dst = (__half2*)(Xcat + (size_t)m * KCAT) + threadIdx.x * 2;
    dst[0] = __floats2half2_rn(v.x, v.y);
    dst[1] = __floats2half2_rn(v.z, v.w);
}

// -------- launch 2: Win0 + Win1 -> fp16 ---------------------------------------
__global__ void cvt_win(const float* __restrict__ Win0, const float* __restrict__ Win1,
                        __half* __restrict__ W0h, __half* __restrict__ W1h)
{
    int i = blockIdx.x * blockDim.x + threadIdx.x;
    const int n4 = Dn * En / 4;
    const float* src; __half* dst; int k;
    if (i < n4) { src = Win0; dst = W0h; k = i; }
    else        { src = Win1; dst = W1h; k = i - n4; }
    float4 v = ((const float4*)src)[k];
    __half2* dp = (__half2*)dst;
    dp[k * 2 + 0] = __floats2half2_rn(v.x, v.y);
    dp[k * 2 + 1] = __floats2half2_rn(v.z, v.w);
}

// -------- launch 3: outW -> fp16  AND  pack [W_x|U0|U1] -> Wcat ---------------
#define NB_OUTW (Vn * Hn / 4 / 256)
__global__ void cvt_whpack(const float* __restrict__ outW, __half* __restrict__ Wh16,
                           const float* __restrict__ Wx, const float* __restrict__ U0,
                           const float* __restrict__ U1, __half* __restrict__ Wcat)
{
    if (blockIdx.x < NB_OUTW) {
        int i = blockIdx.x * 256 + threadIdx.x;
        float4 v = ((const float4*)outW)[i];
        __half2* dp = (__half2*)Wh16;
        dp[i * 2 + 0] = __floats2half2_rn(v.x, v.y);
        dp[i * 2 + 1] = __floats2half2_rn(v.z, v.w);
    } else {
        int n = blockIdx.x - NB_OUTW;
#pragma unroll
        for (int h = 0; h < 2; ++h) {
            int c = (threadIdx.x + h * 256) * 4;
            const float* src;
            if (c < En)            src = Wx + (size_t)n * En + c;
            else if (c < En + Dn)  src = U0 + (size_t)n * Dn + (c - En);
            else                   src = U1 + (size_t)n * Dn + (c - En - Dn);
            float4 v = *(const float4*)src;
            __half2* p = (__half2*)(Wcat + (size_t)n * KCAT + c);
            p[0] = __floats2half2_rn(v.x, v.y);
            p[1] = __floats2half2_rn(v.z, v.w);
        }
    }
}

#define KCH 64
#define TILEB (128 * KCH * 2)
#define STAGEB (2 * TILEB)

// ---- shared tile-GEMM body. flags: 1=bias, 2=accumulate, 4=time->batch remap
__device__ __forceinline__ void gemm_tile(
    uint32_t sbase, int tid, int lane, int wm, int wn,
    const __half* gA, const __half* gB, int lda, int ldb, int K,
    const float* bias, float* C, int ldc, int m0, int n0, int flags)
{
    float acc[4][4][4];
#pragma unroll
    for (int a = 0; a < 4; a++)
#pragma unroll
        for (int bq = 0; bq < 4; bq++)
#pragma unroll
            for (int cx = 0; cx < 4; cx++) acc[a][bq][cx] = 0.f;

    auto issue_stage = [&](int s, int kc) {
        uint32_t stb = sbase + s * STAGEB;
        const __half* ga = gA + kc * KCH;
#pragma unroll
        for (int i = 0; i < 4; ++i) {
            int q = tid + i * 256;
            int r = q >> 3, c = q & 7;
            uint32_t sa = stb + ((r >> 3) << 10) + ((r & 7) << 7) + ((c ^ (r & 7)) << 4);
            cp_async16(sa, ga + (size_t)r * lda + c * 8);
        }
        const __half* gb = gB + kc * KCH;
        uint32_t tb = stb + TILEB;
#pragma unroll
        for (int i = 0; i < 4; ++i) {
            int q = tid + i * 256;
            int r = q >> 3, c = q & 7;
            uint32_t sa = tb + ((r >> 3) << 10) + ((r & 7) << 7) + ((c ^ (r & 7)) << 4);
            cp_async16(sa, gb + (size_t)r * ldb + c * 8);
        }
    };

    issue_stage(0, 0);
    CP_COMMIT();

    const int NKC = K / KCH;
    for (int kc = 0; kc < NKC; ++kc) {
        if (kc + 1 < NKC) { issue_stage((kc + 1) & 1, kc + 1); CP_COMMIT(); CP_WAIT(1); }
        else { CP_WAIT(0); }
        __syncthreads();

        uint32_t sA = sbase + (kc & 1) * STAGEB;
        uint32_t sB = sA + TILEB;

#pragma unroll
        for (int ks = 0; ks < KCH / 16; ++ks) {
            uint32_t ah[4][4], bh[4][2];
            int ra = (lane & 7) + ((lane >> 3) & 1) * 8;
            int ca = ks * 2 + ((lane >> 4) & 1);
#pragma unroll
            for (int mt = 0; mt < 4; ++mt) {
                int row = wm * 64 + mt * 16 + ra;
                uint32_t off = ((row >> 3) << 10) + ((row & 7) << 7)
                             + (((ca ^ (row & 7)) & 7) << 4);
                ldsm_x4(ah[mt][0], ah[mt][1], ah[mt][2], ah[mt][3], sA + off);
            }
            int rb = (lane & 7) + ((lane >> 4) & 1) * 8;
            int cb = ks * 2 + ((lane >> 3) & 1);
#pragma unroll
            for (int np = 0; np < 2; ++np) {
                int row = wn * 32 + np * 16 + rb;
                uint32_t off = ((row >> 3) << 10) + ((row & 7) << 7)
                             + (((cb ^ (row & 7)) & 7) << 4);
                ldsm_x4(bh[np * 2][0], bh[np * 2][1],
                        bh[np * 2 + 1][0], bh[np * 2 + 1][1], sB + off);
            }
#pragma unroll
            for (int mt = 0; mt < 4; ++mt)
#pragma unroll
                for (int nt = 0; nt < 4; ++nt)
                    mma16816h(acc[mt][nt], ah[mt], bh[nt]);
        }
        __syncthreads();
    }

#pragma unroll
    for (int mt = 0; mt < 4; ++mt) {
        int r0g = m0 + wm * 64 + mt * 16 + (lane >> 2);
        int r1g = r0g + 8;
        int row0 = (flags & 4) ? (((r0g & 7) << 9) | (r0g >> 3)) : r0g;
        int row1 = (flags & 4) ? (((r1g & 7) << 9) | (r1g >> 3)) : r1g;
#pragma unroll
        for (int nt = 0; nt < 4; ++nt) {
            int cc = n0 + wn * 32 + nt * 8 + (lane & 3) * 2;
            float bx = 0.f, by = 0.f;
            if (flags & 1) { float2 bia = *(const float2*)(bias + cc); bx = bia.x; by = bia.y; }
            float* p0 = C + (size_t)row0 * ldc + cc;
            float* p1 = C + (size_t)row1 * ldc + cc;
            float2 v0 = make_float2(acc[mt][nt][0] + bx, acc[mt][nt][1] + by);
            float2 v1 = make_float2(acc[mt][nt][2] + bx, acc[mt][nt][3] + by);
            if (flags & 2) {
                float2 o0 = *(float2*)p0, o1 = *(float2*)p1;
                v0.x += o0.x; v0.y += o0.y; v1.x += o1.x; v1.y += o1.y;
            }
            *(float2*)p0 = v0;
            *(float2*)p1 = v1;
        }
    }
}

// -------- launches 4,5: standalone GEMMs --------------------------------------
__global__ void __launch_bounds__(256, 2)
gemm16(const __half* __restrict__ A, const __half* __restrict__ W,
       const float* __restrict__ bias, float* __restrict__ C,
       const __half* __restrict__ W1, float* __restrict__ C1,
       int N, int K, int lda, int ldb, int flags)
{
    extern __shared__ __align__(16) char sm[];
    uint32_t sbase = smem_u32(sm);
    if (blockIdx.z) { W = W1; C = C1; }
    int tid = threadIdx.x, lane = tid & 31, wid = tid >> 5;
    gemm_tile(sbase, tid, lane, wid >> 2, wid & 3,
              A + (size_t)blockIdx.x * 128 * lda, W + (size_t)blockIdx.y * 128 * ldb,
              lda, ldb, K, bias, C, N, blockIdx.x * 128, blockIdx.y * 128, flags);
}

// ---- flag/publish grid barrier (per-CTA distinct flag addresses; one token) --
// Caller guarantees __syncthreads() just before. Token value == steps completed.
__device__ __forceinline__ void flag_barrier(unsigned* flags, unsigned* token,
                                             int bidg, bool isagg,
                                             unsigned tgt, int tid)
{
    if (tid == 0) { __threadfence(); *(volatile unsigned*)(flags + bidg * 32) = tgt; }
    if (isagg) {
        if (tid < 128) {
            volatile unsigned* f = flags + tid * 32;
            while (*f < tgt) {}
        }
        __syncthreads();
        if (tid == 0) { __threadfence(); *(volatile unsigned*)token = tgt; }
        __syncthreads();
    } else {
        if (tid == 0) {
            while (*(volatile unsigned*)token < tgt) __nanosleep(32);
            __threadfence();
        }
        __syncthreads();
    }
}

// -------- launch 6: mega-kernel (R11 roles + flag/publish barriers) -----------
//   bid   0-127: rscan; flag-barrier on g_flagR; token g_tokR == r progress
//   bid 128-255: hscan; gate on g_udone[t>>4]; flag-barrier g_flagH; token g_tokH
//   bid 256-295: U-GEMM workers, gate g_tokR >= 16*(mi+1)
// All drain into logits queue (gate g_tokH >= 16*(mi+1)), epilogue remaps rows.
__global__ void __launch_bounds__(256, 2)
crsd_mega(const float* __restrict__ pre0, const float* __restrict__ pre1,
          const float* __restrict__ Wr0, const float* __restrict__ Wr1,
          float* __restrict__ R0, float* __restrict__ R1,
          __half* __restrict__ Xcat, const __half* __restrict__ Wcat,
          const float* __restrict__ Hpre_c, float* __restrict__ Hpre,
          const float* __restrict__ Whw,
          float* __restrict__ Hout, __half* __restrict__ Hh,
          const __half* __restrict__ Wlg, const float* __restrict__ bias,
          float* __restrict__ C)
{
    extern __shared__ __align__(16) char sm[];
    int bid = blockIdx.x;
    int tid = threadIdx.x, lane = tid & 31, wid = tid >> 5;

    if (bid < 128) {
        // ===================== rscan =====================
        float* smem = (float*)sm;
        float* sW = smem;                 // 8*512
        float* sR = smem + 8 * Dn;        // 8*512
        int res  = bid >> 6;
        int jblk = bid & 63;
        int j0   = jblk * 8;
        const float* pre  = res ? pre1 : pre0;
        const float* Wres = res ? Wr1 : Wr0;
        float* Rout = res ? R1 : R0;
        int b = tid >> 5;

        for (int i = tid; i < 8 * Dn / 4; i += 256)
            ((float4*)sW)[i] = ((const float4*)(Wres + (size_t)j0 * Dn))[i];
        __syncthreads();

        for (int t = 0; t < Tn; ++t) {
            if (t == 0) {
                float4 z = make_float4(0.f, 0.f, 0.f, 0.f);
                for (int i = tid; i < Bn * Dn / 4; i += 256) ((float4*)sR)[i] = z;
            } else {
                const float4* src = (const float4*)(Rout + (size_t)(t - 1) * Bn * Dn);
                for (int i = tid; i < Bn * Dn / 4; i += 256)
                    ((float4*)sR)[i] = __ldcg(src + i);
            }
            __syncthreads();

            const float4* rb = (const float4*)(sR + b * Dn);
            float4 rv[4];
#pragma unroll
            for (int i = 0; i < 4; i++) rv[i] = rb[i * 32 + lane];

            float s[8];
#pragma unroll
            for (int jj = 0; jj < 8; ++jj) {
                const float4* wr = (const float4*)(sW + jj * Dn);
                float sv = 0.f;
#pragma unroll
                for (int i = 0; i < 4; i++) {
                    float4 w4 = wr[i * 32 + lane];
                    sv += rv[i].x * w4.x + rv[i].y * w4.y + rv[i].z * w4.z + rv[i].w * w4.w;
                }
                s[jj] = sv;
            }
#pragma unroll
            for (int off = 16; off; off >>= 1)
#pragma unroll
                for (int jj = 0; jj < 8; ++jj)
                    s[jj] += __shfl_xor_sync(0xffffffffu, s[jj], off);
            float myout = 0.f;
#pragma unroll
            for (int jj = 0; jj < 8; ++jj)
                if (lane == jj) myout = s[jj];

            if (lane < 8) {
                int j = j0 + lane;
                size_t row = (size_t)t * Bn + b;
                float rold = sR[b * Dn + j];
                float p = __ldcg(pre + row * Dn + j);
                float val = 0.5f * rold + 0.5f * tanhf(p + myout);
                Rout[row * Dn + j] = val;
                Xcat[row * KCAT + En + res * Dn + j] = __float2half(val);
            }
            __syncthreads();
            flag_barrier(g_flagR, g_tokR, bid, bid == 0, (unsigned)(t + 1), tid);
        }
        __syncthreads();

    } else if (bid < 256) {
        // ===================== hscan =====================
        float* smem = (float*)sm;
        float* sW = smem;                  // 8*1024
        float* sH = smem + 8 * Hn;         // 8*1024
        int hbid = bid - 128;
        int j0 = hbid * 8;
        int b = tid >> 5;

        for (int i = tid; i < 8 * Hn / 4; i += 256)
            ((float4*)sW)[i] = ((const float4*)(Whw + (size_t)j0 * Hn))[i];
        __syncthreads();

        for (int t = 0; t < Tn; ++t) {
            if ((t & 15) == 0) {
                if (tid == 0) {
                    int mi = t >> 4;
                    while (*(volatile unsigned*)&g_udone[mi] < 8u) __nanosleep(128);
                    __threadfence();
                }
                __syncthreads();
            }
            if (t == 0) {
                float4 z = make_float4(0.f, 0.f, 0.f, 0.f);
                for (int i = tid; i < Bn * Hn / 4; i += 256) ((float4*)sH)[i] = z;
            } else {
                const float4* src = (const float4*)(Hout + (size_t)(t - 1) * Bn * Hn);
                for (int i = tid; i < Bn * Hn / 4; i += 256)
                    ((float4*)sH)[i] = __ldcg(src + i);
            }
            __syncthreads();

            const float4* hb = (const float4*)(sH + b * Hn);
            float4 hv[8];
#pragma unroll
            for (int i = 0; i < 8; i++) hv[i] = hb[i * 32 + lane];

            float s[8];
#pragma unroll
            for (int jj = 0; jj < 8; ++jj) {
                const float4* wr = (const float4*)(sW + jj * Hn);
                float sv = 0.f;
#pragma unroll
                for (int i = 0; i < 8; i++) {
                    float4 w4 = wr[i * 32 + lane];
                    sv += hv[i].x * w4.x + hv[i].y * w4.y + hv[i].z * w4.z + hv[i].w * w4.w;
                }
                s[jj] = sv;
            }
#pragma unroll
            for (int off = 16; off; off >>= 1)
#pragma unroll
                for (int jj = 0; jj < 8; ++jj)
                    s[jj] += __shfl_xor_sync(0xffffffffu, s[jj], off);
            float myout = 0.f;
#pragma unroll
            for (int jj = 0; jj < 8; ++jj)
                if (lane == jj) myout = s[jj];

            if (lane < 8) {
                int j = j0 + lane;
                size_t row = (size_t)t * Bn + b;
                float val = tanhf(__ldcg(Hpre_c + row * Hn + j) + myout);
                Hout[row * Hn + j] = val;
                Hh[row * Hn + j] = __float2half(val);
            }
            __syncthreads();
            flag_barrier(g_flagH, g_tokH, hbid, hbid == 0, (unsigned)(t + 1), tid);
        }
        __syncthreads();

    } else {
        // ===================== U-GEMM workers =====================
        uint32_t sbase = smem_u32(sm);
        int wm = wid >> 2, wn = wid & 3;
        __shared__ unsigned s_ut;
        for (;;) {
            if (tid == 0) s_ut = atomicAdd(&g_uctr, 1u);
            __syncthreads();
            unsigned q = s_ut;
            __syncthreads();
            if (q >= NUTILES) break;
            int mi = q >> 3;
            int ni = q & 7;
            if (tid == 0) {
                unsigned need = (unsigned)(mi + 1) * 16u;
                while (*(volatile unsigned*)g_tokR < need) __nanosleep(128);
            }
            __syncthreads();
            __threadfence();
            gemm_tile(sbase, tid, lane, wm, wn,
                      Xcat + En + (size_t)mi * 128 * KCAT,
                      Wcat + En + (size_t)ni * 128 * KCAT,
                      KCAT, KCAT, 1024, nullptr, Hpre, Hn,
                      mi * 128, ni * 128, 2);
            __threadfence();
            if (tid == 0) atomicAdd(&g_udone[mi], 1u);
            __syncthreads();
        }
    }

    // ===================== logits workers (all CTAs drain) ====================
    uint32_t sbase = smem_u32(sm);
    int wm = wid >> 2, wn = wid & 3;
    __shared__ unsigned s_tile;
    for (;;) {
        if (tid == 0) s_tile = atomicAdd(&g_tilectr, 1u);
        __syncthreads();
        unsigned tile = s_tile;
        __syncthreads();
        if (tile >= NTILES) break;

        int mi = tile / 250;
        int ni = tile % 250;

        if (tid == 0) {
            unsigned need = (unsigned)(mi + 1) * 16u;
            while (*(volatile unsigned*)g_tokH < need) __nanosleep(128);
        }
        __syncthreads();
        __threadfence();

        gemm_tile(sbase, tid, lane, wm, wn,
                  Hh + (size_t)mi * 128 * Hn, Wlg + (size_t)ni * 128 * Hn,
                  Hn, Hn, Hn, bias, C, Vn, mi * 128, ni * 128, 1 | 4);
    }
}

extern "C" void kernel_launch(void* const* d_in, const int* in_sizes, int n_in,
                              void* d_out, int out_size)
{
    const int*   ids   = (const int*)  d_in[0];
    const float* emb   = (const float*)d_in[1];
    const float* W_x   = (const float*)d_in[2];
    const float* W_h   = (const float*)d_in[3];
    const float* b_h   = (const float*)d_in[4];
    const float* Win0  = (const float*)d_in[5];
    const float* Wres0 = (const float*)d_in[6];
    const float* U0    = (const float*)d_in[7];
    const float* Win1  = (const float*)d_in[8];
    const float* Wres1 = (const float*)d_in[9];
    const float* U1    = (const float*)d_in[10];
    const float* outW  = (const float*)d_in[11];
    const float* outb  = (const float*)d_in[12];
    float* out = (float*)d_out;

    float *R0pre, *R1pre, *R0, *R1, *Hpre, *Hst;
    __half *Xcat, *Wcat, *Win0h, *Win1h, *Wh16, *Hh16;
    cudaGetSymbolAddress((void**)&R0pre, g_R0pre);
    cudaGetSymbolAddress((void**)&R1pre, g_R1pre);
    cudaGetSymbolAddress((void**)&R0,    g_R0);
    cudaGetSymbolAddress((void**)&R1,    g_R1);
    cudaGetSymbolAddress((void**)&Hpre,  g_Hpre);
    cudaGetSymbolAddress((void**)&Hst,   g_H);
    cudaGetSymbolAddress((void**)&Xcat,  g_Xcat);
    cudaGetSymbolAddress((void**)&Wcat,  g_Wcat);
    cudaGetSymbolAddress((void**)&Win0h, g_Win0h);
    cudaGetSymbolAddress((void**)&Win1h, g_Win1h);
    cudaGetSymbolAddress((void**)&Wh16,  g_Wh);
    cudaGetSymbolAddress((void**)&Hh16,  g_Hh);

    cudaFuncSetAttribute(gemm16,
                         cudaFuncAttributeMaxDynamicSharedMemorySize, 2 * STAGEB);
    cudaFuncSetAttribute(crsd_mega,
                         cudaFuncAttributeMaxDynamicSharedMemorySize, 2 * STAGEB);

    // (1) embedding gather (time-major) + state reset
    embed_h<<<MROWS, 256>>>(ids, emb, Xcat);

    // (2) Win0/Win1 -> fp16
    cvt_win<<<2 * (Dn * En / 4) / 256, 256>>>(Win0, Win1, Win0h, Win1h);

    // (3) outW -> fp16  +  pack [W_x|U0|U1] -> Wcat
    cvt_whpack<<<NB_OUTW + Hn, 256>>>(outW, Wh16, W_x, U0, U1, Wcat);

    // (4) reservoir input projections (dual via z)
    gemm16<<<dim3(MROWS / 128, Dn / 128, 2), 256, 2 * STAGEB>>>(
        Xcat, Win0h, nullptr, R0pre, Win1h, R1pre, Dn, En, KCAT, En, 0);

    // (5) Hpre_x = X @ W_x^T + b_h
    gemm16<<<dim3(MROWS / 128, Hn / 128, 1), 256, 2 * STAGEB>>>(
        Xcat, Wcat, b_h, Hpre, nullptr, nullptr, Hn, En, KCAT, KCAT, 1);

    // (6) mega-kernel: R11 roles + flag/publish barriers
    crsd_mega<<<296, 256, 2 * STAGEB>>>(
        R0pre, R1pre, Wres0, Wres1, R0, R1, Xcat, Wcat,
        Hpre, Hpre, W_h, Hst, Hh16, Wh16, outb, out);
}

// round 16
// speedup vs baseline: 1.3609x; 1.1603x over previous
#include <cuda_runtime.h>
#include <cuda_fp16.h>
#include <math.h>
#include <stdint.h>

#define Tn 512
#define Bn 8
#define En 1024
#define Hn 1024
#define Dn 512
#define Vn 32000
#define MROWS (Tn * Bn)          // 4096, TIME-MAJOR: row m = t*Bn + b
#define KCAT 2048
#define NMI (MROWS / 128)        // 32 M-tiles, each spans 16 time-steps
#define NTILES (NMI * (Vn / 128))   // 8000 logits tiles
#define NUTILES (NMI * (Hn / 128))  // 256 U tiles

__device__ float g_R0pre[MROWS * Dn];
__device__ float g_R1pre[MROWS * Dn];
__device__ float g_R0[MROWS * Dn];
__device__ float g_R1[MROWS * Dn];
__device__ float g_Hpre[MROWS * Hn];
__device__ float g_H[MROWS * Hn];
__device__ unsigned g_cnt[4];
__device__ unsigned g_done[4];
__device__ unsigned g_prog_r;
__device__ unsigned g_prog;
__device__ unsigned g_uctr;
__device__ unsigned g_udone[NMI];
__device__ unsigned g_tilectr;

__device__ __half g_Xcat[(size_t)MROWS * KCAT];   // [X | R0 | R1] fp16, time-major
__device__ __half g_Wcat[(size_t)Hn * KCAT];      // [W_x | U0 | U1] fp16
__device__ __half g_Win0h[(size_t)Dn * En];
__device__ __half g_Win1h[(size_t)Dn * En];
__device__ __half g_Wh[(size_t)Vn * Hn];
__device__ __half g_Hh[(size_t)MROWS * Hn];

__device__ __forceinline__ uint32_t smem_u32(const void* p) {
    uint32_t a;
    asm("{ .reg .u64 t; cvta.to.shared.u64 t, %1; cvt.u32.u64 %0, t; }" : "=r"(a) : "l"(p));
    return a;
}
__device__ __forceinline__ void cp_async16(uint32_t saddr, const void* gaddr) {
    asm volatile("cp.async.cg.shared.global [%0], [%1], 16;" :: "r"(saddr), "l"(gaddr));
}
#define CP_COMMIT() asm volatile("cp.async.commit_group;" ::: "memory")
#define CP_WAIT(N)  asm volatile("cp.async.wait_group %0;" :: "n"(N) : "memory")

__device__ __forceinline__ void ldsm_x4(uint32_t& r0, uint32_t& r1, uint32_t& r2,
                                        uint32_t& r3, uint32_t addr) {
    asm volatile("ldmatrix.sync.aligned.m8n8.x4.shared.b16 {%0,%1,%2,%3}, [%4];"
                 : "=r"(r0), "=r"(r1), "=r"(r2), "=r"(r3) : "r"(addr));
}
__device__ __forceinline__ void mma16816h(float* c, const uint32_t* a, const uint32_t* b) {
    asm volatile(
        "mma.sync.aligned.m16n8k16.row.col.f32.f16.f16.f32 "
        "{%0,%1,%2,%3}, {%4,%5,%6,%7}, {%8,%9}, {%0,%1,%2,%3};"
        : "+f"(c[0]), "+f"(c[1]), "+f"(c[2]), "+f"(c[3])
        : "r"(a[0]), "r"(a[1]), "r"(a[2]), "r"(a[3]), "r"(b[0]), "r"(b[1]));
}

// -------- launch 1: embedding gather (time-major) + counter reset -------------
__global__ void embed_h(const int* __restrict__ ids, const float* __restrict__ emb,
                        __half* __restrict__ Xcat)
{
    int blk = blockIdx.x;
    if (blk == 0 && threadIdx.x == 0) {
        g_prog_r = 0u; g_prog = 0u; g_uctr = 0u; g_tilectr = 0u;
        for (int i = 0; i < NMI; ++i) g_udone[i] = 0u;
    }
    int b = blk / Tn, t = blk % Tn;
    int m = t * Bn + b;
    int id = __ldg(ids + blk);
    float4 v = __ldg(((const float4*)(emb + (size_t)id * En)) + threadIdx.x);
    __half2* dst = (__half2*)(Xcat + (size_t)m * KCAT) + threadIdx.x * 2;
    dst[0] = __floats2half2_rn(v.x, v.y);
    dst[1] = __floats2half2_rn(v.z, v.w);
}

// -------- launch 2: Win0 + Win1 -> fp16 ---------------------------------------
__global__ void cvt_win(const float* __restrict__ Win0, const float* __restrict__ Win1,
                        __half* __restrict__ W0h, __half* __restrict__ W1h)
{
    int i = blockIdx.x * blockDim.x + threadIdx.x;
    const int n4 = Dn * En / 4;
    const float* src; __half* dst; int k;
    if (i < n4) { src = Win0; dst = W0h; k = i; }
    else        { src = Win1; dst = W1h; k = i - n4; }
    float4 v = ((const float4*)src)[k];
    __half2* dp = (__half2*)dst;
    dp[k * 2 + 0] = __floats2half2_rn(v.x, v.y);
    dp[k * 2 + 1] = __floats2half2_rn(v.z, v.w);
}

// -------- launch 3: outW -> fp16  AND  pack [W_x|U0|U1] -> Wcat ---------------
#define NB_OUTW (Vn * Hn / 4 / 256)
__global__ void cvt_whpack(const float* __restrict__ outW, __half* __restrict__ Wh16,
                           const float* __restrict__ Wx, const float* __restrict__ U0,
                           const float* __restrict__ U1, __half* __restrict__ Wcat)
{
    if (blockIdx.x < NB_OUTW) {
        int i = blockIdx.x * 256 + threadIdx.x;
        float4 v = ((const float4*)outW)[i];
        __half2* dp = (__half2*)Wh16;
        dp[i * 2 + 0] = __floats2half2_rn(v.x, v.y);
        dp[i * 2 + 1] = __floats2half2_rn(v.z, v.w);
    } else {
        int n = blockIdx.x - NB_OUTW;
#pragma unroll
        for (int h = 0; h < 2; ++h) {
            int c = (threadIdx.x + h * 256) * 4;
            const float* src;
            if (c < En)            src = Wx + (size_t)n * En + c;
            else if (c < En + Dn)  src = U0 + (size_t)n * Dn + (c - En);
            else                   src = U1 + (size_t)n * Dn + (c - En - Dn);
            float4 v = *(const float4*)src;
            __half2* p = (__half2*)(Wcat + (size_t)n * KCAT + c);
            p[0] = __floats2half2_rn(v.x, v.y);
            p[1] = __floats2half2_rn(v.z, v.w);
        }
    }
}

#define KCH 64
#define TILEB (128 * KCH * 2)
#define STAGEB (2 * TILEB)

// ---- shared tile-GEMM body. flags: 1=bias, 2=accumulate, 4=time->batch remap
__device__ __forceinline__ void gemm_tile(
    uint32_t sbase, int tid, int lane, int wm, int wn,
    const __half* gA, const __half* gB, int lda, int ldb, int K,
    const float* bias, float* C, int ldc, int m0, int n0, int flags)
{
    float acc[4][4][4];
#pragma unroll
    for (int a = 0; a < 4; a++)
#pragma unroll
        for (int bq = 0; bq < 4; bq++)
#pragma unroll
            for (int cx = 0; cx < 4; cx++) acc[a][bq][cx] = 0.f;

    auto issue_stage = [&](int s, int kc) {
        uint32_t stb = sbase + s * STAGEB;
        const __half* ga = gA + kc * KCH;
#pragma unroll
        for (int i = 0; i < 4; ++i) {
            int q = tid + i * 256;
            int r = q >> 3, c = q & 7;
            uint32_t sa = stb + ((r >> 3) << 10) + ((r & 7) << 7) + ((c ^ (r & 7)) << 4);
            cp_async16(sa, ga + (size_t)r * lda + c * 8);
        }
        const __half* gb = gB + kc * KCH;
        uint32_t tb = stb + TILEB;
#pragma unroll
        for (int i = 0; i < 4; ++i) {
            int q = tid + i * 256;
            int r = q >> 3, c = q & 7;
            uint32_t sa = tb + ((r >> 3) << 10) + ((r & 7) << 7) + ((c ^ (r & 7)) << 4);
            cp_async16(sa, gb + (size_t)r * ldb + c * 8);
        }
    };

    issue_stage(0, 0);
    CP_COMMIT();

    const int NKC = K / KCH;
    for (int kc = 0; kc < NKC; ++kc) {
        if (kc + 1 < NKC) { issue_stage((kc + 1) & 1, kc + 1); CP_COMMIT(); CP_WAIT(1); }
        else { CP_WAIT(0); }
        __syncthreads();

        uint32_t sA = sbase + (kc & 1) * STAGEB;
        uint32_t sB = sA + TILEB;

#pragma unroll
        for (int ks = 0; ks < KCH / 16; ++ks) {
            uint32_t ah[4][4], bh[4][2];
            int ra = (lane & 7) + ((lane >> 3) & 1) * 8;
            int ca = ks * 2 + ((lane >> 4) & 1);
#pragma unroll
            for (int mt = 0; mt < 4; ++mt) {
                int row = wm * 64 + mt * 16 + ra;
                uint32_t off = ((row >> 3) << 10) + ((row & 7) << 7)
                             + (((ca ^ (row & 7)) & 7) << 4);
                ldsm_x4(ah[mt][0], ah[mt][1], ah[mt][2], ah[mt][3], sA + off);
            }
            int rb = (lane & 7) + ((lane >> 4) & 1) * 8;
            int cb = ks * 2 + ((lane >> 3) & 1);
#pragma unroll
            for (int np = 0; np < 2; ++np) {
                int row = wn * 32 + np * 16 + rb;
                uint32_t off = ((row >> 3) << 10) + ((row & 7) << 7)
                             + (((cb ^ (row & 7)) & 7) << 4);
                ldsm_x4(bh[np * 2][0], bh[np * 2][1],
                        bh[np * 2 + 1][0], bh[np * 2 + 1][1], sB + off);
            }
#pragma unroll
            for (int mt = 0; mt < 4; ++mt)
#pragma unroll
                for (int nt = 0; nt < 4; ++nt)
                    mma16816h(acc[mt][nt], ah[mt], bh[nt]);
        }
        __syncthreads();
    }

#pragma unroll
    for (int mt = 0; mt < 4; ++mt) {
        int r0g = m0 + wm * 64 + mt * 16 + (lane >> 2);
        int r1g = r0g + 8;
        int row0 = (flags & 4) ? (((r0g & 7) << 9) | (r0g >> 3)) : r0g;
        int row1 = (flags & 4) ? (((r1g & 7) << 9) | (r1g >> 3)) : r1g;
#pragma unroll
        for (int nt = 0; nt < 4; ++nt) {
            int cc = n0 + wn * 32 + nt * 8 + (lane & 3) * 2;
            float bx = 0.f, by = 0.f;
            if (flags & 1) { float2 bia = *(const float2*)(bias + cc); bx = bia.x; by = bia.y; }
            float* p0 = C + (size_t)row0 * ldc + cc;
            float* p1 = C + (size_t)row1 * ldc + cc;
            float2 v0 = make_float2(acc[mt][nt][0] + bx, acc[mt][nt][1] + by);
            float2 v1 = make_float2(acc[mt][nt][2] + bx, acc[mt][nt][3] + by);
            if (flags & 2) {
                float2 o0 = *(float2*)p0, o1 = *(float2*)p1;
                v0.x += o0.x; v0.y += o0.y; v1.x += o1.x; v1.y += o1.y;
            }
            *(float2*)p0 = v0;
            *(float2*)p1 = v1;
        }
    }
}

// -------- launches 4,5: standalone GEMMs --------------------------------------
__global__ void __launch_bounds__(256, 2)
gemm16(const __half* __restrict__ A, const __half* __restrict__ W,
       const float* __restrict__ bias, float* __restrict__ C,
       const __half* __restrict__ W1, float* __restrict__ C1,
       int N, int K, int lda, int ldb, int flags)
{
    extern __shared__ __align__(16) char sm[];
    uint32_t sbase = smem_u32(sm);
    if (blockIdx.z) { W = W1; C = C1; }
    int tid = threadIdx.x, lane = tid & 31, wid = tid >> 5;
    gemm_tile(sbase, tid, lane, wid >> 2, wid & 3,
              A + (size_t)blockIdx.x * 128 * lda, W + (size_t)blockIdx.y * 128 * ldb,
              lda, ldb, K, bias, C, N, blockIdx.x * 128, blockIdx.y * 128, flags);
}

__device__ __forceinline__ void gbar_arrive_wait(unsigned* cnt, unsigned target)
{
    if (threadIdx.x == 0) {
        __threadfence();
        atomicAdd(cnt, 1u);
        while (*(volatile unsigned*)cnt < target) __nanosleep(32);
        __threadfence();
    }
    __syncthreads();
}
__device__ __forceinline__ void gbar_reset(unsigned* cnt, unsigned* done, unsigned nctas)
{
    if (threadIdx.x == 0) {
        unsigned v = atomicAdd(done, 1u);
        if (v == nctas - 1u) { *done = 0u; *cnt = 0u; __threadfence(); }
    }
}

// -------- launch 6: mega-kernel (R11 + placement-clean role permutation) ------
// Classic placement: SM = LUT[bid % 148]. Role map chosen so scan CTAs pair
// ONLY with scan CTAs on their SM:
//   bids   0-127 : rscan   (SMs L[0..127], wave 1)
//   bids 148-275 : hscan   (SMs L[0..127], wave 2)  -> rscan+hscan pairs
//   bids 128-147 & 276-295 : U/logits workers (SMs L[128..147], worker pairs)
__global__ void __launch_bounds__(256, 2)
crsd_mega(const float* __restrict__ pre0, const float* __restrict__ pre1,
          const float* __restrict__ Wr0, const float* __restrict__ Wr1,
          float* __restrict__ R0, float* __restrict__ R1,
          __half* __restrict__ Xcat, const __half* __restrict__ Wcat,
          const float* __restrict__ Hpre_c, float* __restrict__ Hpre,
          const float* __restrict__ Whw,
          float* __restrict__ Hout, __half* __restrict__ Hh,
          const __half* __restrict__ Wlg, const float* __restrict__ bias,
          float* __restrict__ C)
{
    extern __shared__ __align__(16) char sm[];
    int bid = blockIdx.x;
    int tid = threadIdx.x, lane = tid & 31, wid = tid >> 5;

    bool is_rscan = (bid < 128);
    bool is_hscan = (bid >= 148 && bid < 276);

    if (is_rscan) {
        // ===================== rscan =====================
        float* smem = (float*)sm;
        float* sW = smem;                 // 8*512
        float* sR = smem + 8 * Dn;        // 8*512
        int res  = bid >> 6;
        int jblk = bid & 63;
        int j0   = jblk * 8;
        const float* pre  = res ? pre1 : pre0;
        const float* Wres = res ? Wr1 : Wr0;
        float* Rout = res ? R1 : R0;
        int b = tid >> 5;

        for (int i = tid; i < 8 * Dn / 4; i += 256)
            ((float4*)sW)[i] = ((const float4*)(Wres + (size_t)j0 * Dn))[i];
        __syncthreads();

        for (int t = 0; t < Tn; ++t) {
            if (t == 0) {
                float4 z = make_float4(0.f, 0.f, 0.f, 0.f);
                for (int i = tid; i < Bn * Dn / 4; i += 256) ((float4*)sR)[i] = z;
            } else {
                const float4* src = (const float4*)(Rout + (size_t)(t - 1) * Bn * Dn);
                for (int i = tid; i < Bn * Dn / 4; i += 256)
                    ((float4*)sR)[i] = __ldcg(src + i);
            }
            __syncthreads();

            const float4* rb = (const float4*)(sR + b * Dn);
            float4 rv[4];
#pragma unroll
            for (int i = 0; i < 4; i++) rv[i] = rb[i * 32 + lane];

            float myout = 0.f;
#pragma unroll
            for (int jj = 0; jj < 8; ++jj) {
                const float4* wr = (const float4*)(sW + jj * Dn);
                float sv = 0.f;
#pragma unroll
                for (int i = 0; i < 4; i++) {
                    float4 w4 = wr[i * 32 + lane];
                    sv += rv[i].x * w4.x + rv[i].y * w4.y + rv[i].z * w4.z + rv[i].w * w4.w;
                }
#pragma unroll
                for (int off = 16; off; off >>= 1) sv += __shfl_xor_sync(0xffffffffu, sv, off);
                if (lane == jj) myout = sv;
            }
            if (lane < 8) {
                int j = j0 + lane;
                size_t row = (size_t)t * Bn + b;
                float rold = sR[b * Dn + j];
                float p = __ldcg(pre + row * Dn + j);
                float val = 0.5f * rold + 0.5f * tanhf(p + myout);
                Rout[row * Dn + j] = val;
                Xcat[row * KCAT + En + res * Dn + j] = __float2half(val);
            }
            __syncthreads();
            gbar_arrive_wait(&g_cnt[0], 128u * (unsigned)(t + 1));
            if (bid == 0 && tid == 0)
                *(volatile unsigned*)&g_prog_r = (unsigned)(t + 1);
        }
        gbar_reset(&g_cnt[0], &g_done[0], 128u);
        __syncthreads();

    } else if (is_hscan) {
        // ===================== hscan =====================
        float* smem = (float*)sm;
        float* sW = smem;                  // 8*1024
        float* sH = smem + 8 * Hn;         // 8*1024
        int hbid = bid - 148;              // 0..127
        int j0 = hbid * 8;
        int b = tid >> 5;

        for (int i = tid; i < 8 * Hn / 4; i += 256)
            ((float4*)sW)[i] = ((const float4*)(Whw + (size_t)j0 * Hn))[i];
        __syncthreads();

        for (int t = 0; t < Tn; ++t) {
            if ((t & 15) == 0) {
                if (tid == 0) {
                    int mi = t >> 4;
                    while (*(volatile unsigned*)&g_udone[mi] < 8u) __nanosleep(128);
                    __threadfence();
                }
                __syncthreads();
            }
            if (t == 0) {
                float4 z = make_float4(0.f, 0.f, 0.f, 0.f);
                for (int i = tid; i < Bn * Hn / 4; i += 256) ((float4*)sH)[i] = z;
            } else {
                const float4* src = (const float4*)(Hout + (size_t)(t - 1) * Bn * Hn);
                for (int i = tid; i < Bn * Hn / 4; i += 256)
                    ((float4*)sH)[i] = __ldcg(src + i);
            }
            __syncthreads();

            const float4* hb = (const float4*)(sH + b * Hn);
            float4 hv[8];
#pragma unroll
            for (int i = 0; i < 8; i++) hv[i] = hb[i * 32 + lane];

            float myout = 0.f;
#pragma unroll
            for (int jj = 0; jj < 8; ++jj) {
                const float4* wr = (const float4*)(sW + jj * Hn);
                float sv = 0.f;
#pragma unroll
                for (int i = 0; i < 8; i++) {
                    float4 w4 = wr[i * 32 + lane];
                    sv += hv[i].x * w4.x + hv[i].y * w4.y + hv[i].z * w4.z + hv[i].w * w4.w;
                }
#pragma unroll
                for (int off = 16; off; off >>= 1) sv += __shfl_xor_sync(0xffffffffu, sv, off);
                if (lane == jj) myout = sv;
            }
            if (lane < 8) {
                int j = j0 + lane;
                size_t row = (size_t)t * Bn + b;
                float val = tanhf(__ldcg(Hpre_c + row * Hn + j) + myout);
                Hout[row * Hn + j] = val;
                Hh[row * Hn + j] = __float2half(val);
            }
            __syncthreads();
            gbar_arrive_wait(&g_cnt[2], 128u * (unsigned)(t + 1));
            if (hbid == 0 && tid == 0)
                *(volatile unsigned*)&g_prog = (unsigned)(t + 1);
        }
        gbar_reset(&g_cnt[2], &g_done[2], 128u);
        __syncthreads();

    } else {
        // ===================== U-GEMM workers (bids 128-147, 276-295) =========
        uint32_t sbase = smem_u32(sm);
        int wm = wid >> 2, wn = wid & 3;
        __shared__ unsigned s_ut;
        for (;;) {
            if (tid == 0) s_ut = atomicAdd(&g_uctr, 1u);
            __syncthreads();
            unsigned q = s_ut;
            __syncthreads();
            if (q >= NUTILES) break;
            int mi = q >> 3;
            int ni = q & 7;
            if (tid == 0) {
                unsigned need = (unsigned)(mi + 1) * 16u;
                while (*(volatile unsigned*)&g_prog_r < need) __nanosleep(128);
            }
            __syncthreads();
            __threadfence();
            gemm_tile(sbase, tid, lane, wm, wn,
                      Xcat + En + (size_t)mi * 128 * KCAT,
                      Wcat + En + (size_t)ni * 128 * KCAT,
                      KCAT, KCAT, 1024, nullptr, Hpre, Hn,
                      mi * 128, ni * 128, 2);
            __threadfence();
            if (tid == 0) atomicAdd(&g_udone[mi], 1u);
            __syncthreads();
        }
    }

    // ===================== logits workers (all CTAs drain) ====================
    uint32_t sbase = smem_u32(sm);
    int wm = wid >> 2, wn = wid & 3;
    __shared__ unsigned s_tile;
    for (;;) {
        if (tid == 0) s_tile = atomicAdd(&g_tilectr, 1u);
        __syncthreads();
        unsigned tile = s_tile;
        __syncthreads();
        if (tile >= NTILES) break;

        int mi = tile / 250;
        int ni = tile % 250;

        if (tid == 0) {
            unsigned need = (unsigned)(mi + 1) * 16u;
            while (*(volatile unsigned*)&g_prog < need) __nanosleep(128);
        }
        __syncthreads();
        __threadfence();

        gemm_tile(sbase, tid, lane, wm, wn,
                  Hh + (size_t)mi * 128 * Hn, Wlg + (size_t)ni * 128 * Hn,
                  Hn, Hn, Hn, bias, C, Vn, mi * 128, ni * 128, 1 | 4);
    }
}

extern "C" void kernel_launch(void* const* d_in, const int* in_sizes, int n_in,
                              void* d_out, int out_size)
{
    const int*   ids   = (const int*)  d_in[0];
    const float* emb   = (const float*)d_in[1];
    const float* W_x   = (const float*)d_in[2];
    const float* W_h   = (const float*)d_in[3];
    const float* b_h   = (const float*)d_in[4];
    const float* Win0  = (const float*)d_in[5];
    const float* Wres0 = (const float*)d_in[6];
    const float* U0    = (const float*)d_in[7];
    const float* Win1  = (const float*)d_in[8];
    const float* Wres1 = (const float*)d_in[9];
    const float* U1    = (const float*)d_in[10];
    const float* outW  = (const float*)d_in[11];
    const float* outb  = (const float*)d_in[12];
    float* out = (float*)d_out;

    float *R0pre, *R1pre, *R0, *R1, *Hpre, *Hst;
    __half *Xcat, *Wcat, *Win0h, *Win1h, *Wh16, *Hh16;
    cudaGetSymbolAddress((void**)&R0pre, g_R0pre);
    cudaGetSymbolAddress((void**)&R1pre, g_R1pre);
    cudaGetSymbolAddress((void**)&R0,    g_R0);
    cudaGetSymbolAddress((void**)&R1,    g_R1);
    cudaGetSymbolAddress((void**)&Hpre,  g_Hpre);
    cudaGetSymbolAddress((void**)&Hst,   g_H);
    cudaGetSymbolAddress((void**)&Xcat,  g_Xcat);
    cudaGetSymbolAddress((void**)&Wcat,  g_Wcat);
    cudaGetSymbolAddress((void**)&Win0h, g_Win0h);
    cudaGetSymbolAddress((void**)&Win1h, g_Win1h);
    cudaGetSymbolAddress((void**)&Wh16,  g_Wh);
    cudaGetSymbolAddress((void**)&Hh16,  g_Hh);

    cudaFuncSetAttribute(gemm16,
                         cudaFuncAttributeMaxDynamicSharedMemorySize, 2 * STAGEB);
    cudaFuncSetAttribute(crsd_mega,
                         cudaFuncAttributeMaxDynamicSharedMemorySize, 2 * STAGEB);

    // (1) embedding gather (time-major) + counter reset
    embed_h<<<MROWS, 256>>>(ids, emb, Xcat);

    // (2) Win0/Win1 -> fp16
    cvt_win<<<2 * (Dn * En / 4) / 256, 256>>>(Win0, Win1, Win0h, Win1h);

    // (3) outW -> fp16  +  pack [W_x|U0|U1] -> Wcat
    cvt_whpack<<<NB_OUTW + Hn, 256>>>(outW, Wh16, W_x, U0, U1, Wcat);

    // (4) reservoir input projections (dual via z)
    gemm16<<<dim3(MROWS / 128, Dn / 128, 2), 256, 2 * STAGEB>>>(
        Xcat, Win0h, nullptr, R0pre, Win1h, R1pre, Dn, En, KCAT, En, 0);

    // (5) Hpre_x = X @ W_x^T + b_h
    gemm16<<<dim3(MROWS / 128, Hn / 128, 1), 256, 2 * STAGEB>>>(
        Xcat, Wcat, b_h, Hpre, nullptr, nullptr, Hn, En, KCAT, KCAT, 1);

    // (6) mega-kernel: placement-clean role permutation of R11
    crsd_mega<<<296, 256, 2 * STAGEB>>>(
        R0pre, R1pre, Wres0, Wres1, R0, R1, Xcat, Wcat,
        Hpre, Hpre, W_h, Hst, Hh16, Wh16, outb, out);
}